// round 2
// baseline (speedup 1.0000x reference)
#include <cuda_runtime.h>
#include <math.h>

#define N 8192
#define D 64
#define BM 64
#define SCALE 0.125f   // 1/sqrt(64)

// ---------------- scratch (static device globals; no allocation) ----------------
__device__ float g_Q[2][N * D];      // projected queries for x(0) / y(1)
__device__ float g_K[2][N * D];      // projected keys
__device__ float g_att[2][N * D];    // attention outputs
__device__ float g_norm[2][N];       // row squared norms of attention outputs

// ---------------- kernel 1: Q/K projection for both x and y ----------------
// grid = 2 * N/4 blocks, 256 threads. Each block: 4 rows, 64 cols, both W's.
__global__ __launch_bounds__(256) void proj_kernel(const float* __restrict__ x,
                                                   const float* __restrict__ y,
                                                   const float* __restrict__ Wq,
                                                   const float* __restrict__ Wk) {
    __shared__ float sWq[D * D];
    __shared__ float sWk[D * D];
    __shared__ float sIn[4][D];
    int tid = threadIdx.x;
    int b = blockIdx.x;
    int which = (b >= (N / 4)) ? 1 : 0;
    const float* in = which ? y : x;
    int row0 = (which ? b - N / 4 : b) * 4;

    for (int i = tid; i < D * D; i += 256) { sWq[i] = Wq[i]; sWk[i] = Wk[i]; }
    {
        int r = tid >> 6, c = tid & 63;
        sIn[r][c] = in[(row0 + r) * D + c];
    }
    __syncthreads();

    int r = tid >> 6, c = tid & 63;
    float aq = 0.f, ak = 0.f;
#pragma unroll
    for (int k = 0; k < D; k++) {
        float v = sIn[r][k];
        aq = fmaf(v, sWq[k * D + c], aq);
        ak = fmaf(v, sWk[k * D + c], ak);
    }
    g_Q[which][(row0 + r) * D + c] = aq;
    g_K[which][(row0 + r) * D + c] = ak;
}

// ---------------- kernel 2: flash attention (online softmax), fp32 ----------------
// grid = 2 * N/BM blocks (x then y), 256 threads (16x16), 4x4 micro-tile.
struct FlashSmem {
    float Qs[BM][D + 1];
    float Ks[BM][D + 1];
    float Vs[BM][D + 1];
    float Ps[BM][D + 1];
    float m[BM];
    float l[BM];
    float f[BM];
};

__global__ __launch_bounds__(256) void flash_kernel(const float* __restrict__ x,
                                                    const float* __restrict__ y) {
    extern __shared__ char smem_raw[];
    FlashSmem& sm = *reinterpret_cast<FlashSmem*>(smem_raw);

    int tid = threadIdx.x;
    int b = blockIdx.x;
    int which = (b >= (N / BM)) ? 1 : 0;
    int qb = which ? b - N / BM : b;
    const float* V = which ? y : x;
    const float* Q = g_Q[which];
    const float* K = g_K[which];
    int qrow0 = qb * BM;

    for (int i = tid; i < BM * D; i += 256)
        sm.Qs[i >> 6][i & 63] = Q[qrow0 * D + i];
    if (tid < BM) { sm.m[tid] = -INFINITY; sm.l[tid] = 0.f; }

    int ty = tid >> 4, tx = tid & 15;
    int r0 = ty * 4, c0 = tx * 4, d0 = tx * 4;
    float o[4][4] = {};

    for (int j0 = 0; j0 < N; j0 += BM) {
        __syncthreads();  // previous iteration's readers done; Qs/m/l ready (iter 0)
        for (int i = tid; i < BM * D; i += 256) {
            sm.Ks[i >> 6][i & 63] = K[j0 * D + i];
            sm.Vs[i >> 6][i & 63] = V[j0 * D + i];
        }
        __syncthreads();

        // S tile: 64x64, 4x4 per thread
        float s[4][4] = {};
#pragma unroll
        for (int k = 0; k < D; k++) {
            float qv[4], kv[4];
#pragma unroll
            for (int i = 0; i < 4; i++) qv[i] = sm.Qs[r0 + i][k];
#pragma unroll
            for (int j = 0; j < 4; j++) kv[j] = sm.Ks[c0 + j][k];
#pragma unroll
            for (int i = 0; i < 4; i++)
#pragma unroll
                for (int j = 0; j < 4; j++) s[i][j] = fmaf(qv[i], kv[j], s[i][j]);
        }
#pragma unroll
        for (int i = 0; i < 4; i++)
#pragma unroll
            for (int j = 0; j < 4; j++) sm.Ps[r0 + i][c0 + j] = s[i][j] * SCALE;
        __syncthreads();

        // online softmax per row (64 threads, one row each)
        if (tid < BM) {
            float mo = sm.m[tid];
            float mx = mo;
            for (int c = 0; c < BM; c++) mx = fmaxf(mx, sm.Ps[tid][c]);
            float fac = __expf(mo - mx);
            float sum = 0.f;
            for (int c = 0; c < BM; c++) {
                float p = __expf(sm.Ps[tid][c] - mx);
                sm.Ps[tid][c] = p;
                sum += p;
            }
            sm.l[tid] = sm.l[tid] * fac + sum;
            sm.m[tid] = mx;
            sm.f[tid] = fac;
        }
        __syncthreads();

        // rescale accumulators and add P @ V
        float fr[4];
#pragma unroll
        for (int i = 0; i < 4; i++) fr[i] = sm.f[r0 + i];
#pragma unroll
        for (int i = 0; i < 4; i++)
#pragma unroll
            for (int j = 0; j < 4; j++) o[i][j] *= fr[i];

        for (int c = 0; c < BM; c++) {
            float vv[4];
#pragma unroll
            for (int j = 0; j < 4; j++) vv[j] = sm.Vs[c][d0 + j];
#pragma unroll
            for (int i = 0; i < 4; i++) {
                float p = sm.Ps[r0 + i][c];
#pragma unroll
                for (int j = 0; j < 4; j++) o[i][j] = fmaf(p, vv[j], o[i][j]);
            }
        }
    }
    __syncthreads();

    float li[4];
#pragma unroll
    for (int i = 0; i < 4; i++) li[i] = 1.f / sm.l[r0 + i];
#pragma unroll
    for (int i = 0; i < 4; i++)
#pragma unroll
        for (int j = 0; j < 4; j++)
            g_att[which][(qrow0 + r0 + i) * D + d0 + j] = o[i][j] * li[i];
}

// ---------------- kernel 3: squared row norms of attention outputs ----------------
__global__ __launch_bounds__(256) void norm_kernel() {
    int i = blockIdx.x * 256 + threadIdx.x;  // 0 .. 2N-1
    int which = (i >= N) ? 1 : 0;
    int r = which ? i - N : i;
    float s = 0.f;
#pragma unroll
    for (int k = 0; k < D; k++) {
        float v = g_att[which][r * D + k];
        s = fmaf(v, v, s);
    }
    g_norm[which][r] = s;
}

// ---------------- kernel 4: pairwise RBF kernel matrix ----------------
// grid (N/64, N/64), 256 threads, 4x4 micro-tile, float4 stores.
__global__ __launch_bounds__(256) void pairwise_kernel(float* __restrict__ out) {
    __shared__ float Xs[64][D + 1];
    __shared__ float Ys[64][D + 1];
    __shared__ float xn[64];
    __shared__ float yn[64];
    int tid = threadIdx.x;
    int xrow0 = blockIdx.y * 64;
    int yrow0 = blockIdx.x * 64;

    for (int i = tid; i < 64 * D; i += 256) {
        Xs[i >> 6][i & 63] = g_att[0][xrow0 * D + i];
        Ys[i >> 6][i & 63] = g_att[1][yrow0 * D + i];
    }
    if (tid < 64) {
        xn[tid] = g_norm[0][xrow0 + tid];
        yn[tid] = g_norm[1][yrow0 + tid];
    }
    __syncthreads();

    int ty = tid >> 4, tx = tid & 15;
    int r0 = ty * 4, c0 = tx * 4;
    float acc[4][4] = {};
#pragma unroll
    for (int k = 0; k < D; k++) {
        float xv[4], yv[4];
#pragma unroll
        for (int i = 0; i < 4; i++) xv[i] = Xs[r0 + i][k];
#pragma unroll
        for (int j = 0; j < 4; j++) yv[j] = Ys[c0 + j][k];
#pragma unroll
        for (int i = 0; i < 4; i++)
#pragma unroll
            for (int j = 0; j < 4; j++) acc[i][j] = fmaf(xv[i], yv[j], acc[i][j]);
    }

#pragma unroll
    for (int i = 0; i < 4; i++) {
        float4 res;
        float a = xn[r0 + i];
        res.x = __expf(-(a + yn[c0 + 0] - 2.f * acc[i][0]));
        res.y = __expf(-(a + yn[c0 + 1] - 2.f * acc[i][1]));
        res.z = __expf(-(a + yn[c0 + 2] - 2.f * acc[i][2]));
        res.w = __expf(-(a + yn[c0 + 3] - 2.f * acc[i][3]));
        size_t row = (size_t)(xrow0 + r0 + i);
        *reinterpret_cast<float4*>(&out[row * N + yrow0 + c0]) = res;
    }
}

// ---------------- launch ----------------
extern "C" void kernel_launch(void* const* d_in, const int* in_sizes, int n_in,
                              void* d_out, int out_size) {
    const float* Wq = (const float*)d_in[0];  // rotation_params
    const float* Wk = (const float*)d_in[1];  // entangle_params
    const float* x  = (const float*)d_in[2];
    const float* y  = (const float*)d_in[3];
    float* out = (float*)d_out;

    proj_kernel<<<2 * N / 4, 256>>>(x, y, Wq, Wk);

    int flash_smem = (int)sizeof(FlashSmem);
    cudaFuncSetAttribute(flash_kernel, cudaFuncAttributeMaxDynamicSharedMemorySize,
                         flash_smem);
    flash_kernel<<<2 * N / BM, 256, flash_smem>>>(x, y);

    norm_kernel<<<2 * N / 256, 256>>>();

    dim3 grid(N / 64, N / 64);
    pairwise_kernel<<<grid, 256>>>(out);
}

// round 4
// speedup vs baseline: 3.6897x; 3.6897x over previous
#include <cuda_runtime.h>
#include <cuda_bf16.h>
#include <cstdint>
#include <math.h>

#define N 8192
#define D 64
#define SCALE 0.125f      // 1/sqrt(64)
#define LSTRIDE 72        // smem row stride in bf16 elements (144B, conflict-free)
#define LS32 36           // LSTRIDE/2, in u32 units

// ---------------------------------------------------------------------------
// global scratch (no allocation allowed)
// ---------------------------------------------------------------------------
__device__ __nv_bfloat16 g_qhi[2][N * D];
__device__ __nv_bfloat16 g_qlo[2][N * D];
__device__ __nv_bfloat16 g_khi[2][N * D];
__device__ __nv_bfloat16 g_klo[2][N * D];
__device__ __nv_bfloat16 g_vthi[2][D * N];   // V^T: [d][n]
__device__ __nv_bfloat16 g_vtlo[2][D * N];
__device__ __nv_bfloat16 g_atthi[2][N * D];
__device__ __nv_bfloat16 g_attlo[2][N * D];
__device__ float g_norm2[2][N];

// ---------------------------------------------------------------------------
// helpers
// ---------------------------------------------------------------------------
__device__ __forceinline__ void mma16816(float* c, const uint32_t* a, const uint32_t* b) {
    asm volatile(
        "mma.sync.aligned.m16n8k16.row.col.f32.bf16.bf16.f32 "
        "{%0,%1,%2,%3}, {%4,%5,%6,%7}, {%8,%9}, {%0,%1,%2,%3};\n"
        : "+f"(c[0]), "+f"(c[1]), "+f"(c[2]), "+f"(c[3])
        : "r"(a[0]), "r"(a[1]), "r"(a[2]), "r"(a[3]), "r"(b[0]), "r"(b[1]));
}
// pack two floats into bf16x2: low half = lo, high half = hi
__device__ __forceinline__ uint32_t pack_bf16x2(float lo, float hi) {
    uint32_t r;
    asm("cvt.rn.bf16x2.f32 %0, %1, %2;" : "=r"(r) : "f"(hi), "f"(lo));
    return r;
}
__device__ __forceinline__ float lo_bf16(uint32_t p) { return __uint_as_float(p << 16); }
__device__ __forceinline__ float hi_bf16(uint32_t p) { return __uint_as_float(p & 0xFFFF0000u); }

__device__ __forceinline__ void split2(float v, __nv_bfloat16& h, __nv_bfloat16& l) {
    h = __float2bfloat16(v);
    l = __float2bfloat16(v - __bfloat162float(h));
}

// ---------------------------------------------------------------------------
// kernel 1: Q/K projection + bf16 splits + transposed V splits
// ---------------------------------------------------------------------------
__global__ __launch_bounds__(256) void prep_kernel(const float* __restrict__ x,
                                                   const float* __restrict__ y,
                                                   const float* __restrict__ Wq,
                                                   const float* __restrict__ Wk) {
    __shared__ float sWq[D * D];
    __shared__ float sWk[D * D];
    __shared__ float sIn[4][D];
    int tid = threadIdx.x;
    int b = blockIdx.x;
    int which = (b >= (N / 4)) ? 1 : 0;
    const float* in = which ? y : x;
    int row0 = (which ? b - N / 4 : b) * 4;

    for (int i = tid; i < D * D; i += 256) { sWq[i] = Wq[i]; sWk[i] = Wk[i]; }
    int r = tid >> 6, c = tid & 63;
    sIn[r][c] = in[(row0 + r) * D + c];
    __syncthreads();

    float aq = 0.f, ak = 0.f;
#pragma unroll
    for (int k = 0; k < D; k++) {
        float v = sIn[r][k];
        aq = fmaf(v, sWq[k * D + c], aq);
        ak = fmaf(v, sWk[k * D + c], ak);
    }
    int n = row0 + r;
    __nv_bfloat16 h, l;
    split2(aq, h, l); g_qhi[which][n * D + c] = h; g_qlo[which][n * D + c] = l;
    split2(ak, h, l); g_khi[which][n * D + c] = h; g_klo[which][n * D + c] = l;
    split2(sIn[r][c], h, l);
    g_vthi[which][c * N + n] = h; g_vtlo[which][c * N + n] = l;
}

// ---------------------------------------------------------------------------
// kernel 2: single-pass flash attention with mma.sync bf16 splits
// CTA: 128 threads (4 warps), 64 query rows (16 per warp), BN=64 key tiles.
// ---------------------------------------------------------------------------
__global__ __launch_bounds__(128, 2) void flash_mma_kernel() {
    __shared__ __nv_bfloat16 sKh[64 * LSTRIDE];
    __shared__ __nv_bfloat16 sKl[64 * LSTRIDE];
    __shared__ __nv_bfloat16 sVh[64 * LSTRIDE];
    __shared__ __nv_bfloat16 sVl[64 * LSTRIDE];

    int tid = threadIdx.x;
    int w = tid >> 5, lane = tid & 31;
    int q = lane >> 2, c = lane & 3;
    int which = blockIdx.x >> 7;
    int q0 = (blockIdx.x & 127) * 64;
    int rowA = w * 16 + q;

    // stage Q tile (hi/lo) and extract A fragments into registers
    for (int u = tid; u < 512; u += 128) {
        int r = u >> 3, ch = u & 7;
        ((uint4*)(sKh + r * LSTRIDE))[ch] = ((const uint4*)(g_qhi[which] + (size_t)(q0 + r) * D))[ch];
        ((uint4*)(sKl + r * LSTRIDE))[ch] = ((const uint4*)(g_qlo[which] + (size_t)(q0 + r) * D))[ch];
    }
    __syncthreads();

    uint32_t aq[2][4][4];
    {
        const uint32_t* ph = (const uint32_t*)sKh;
        const uint32_t* pl = (const uint32_t*)sKl;
#pragma unroll
        for (int kk = 0; kk < 4; kk++) {
            int col = kk * 8 + c;
            aq[0][kk][0] = ph[rowA * LS32 + col];
            aq[0][kk][1] = ph[(rowA + 8) * LS32 + col];
            aq[0][kk][2] = ph[rowA * LS32 + col + 4];
            aq[0][kk][3] = ph[(rowA + 8) * LS32 + col + 4];
            aq[1][kk][0] = pl[rowA * LS32 + col];
            aq[1][kk][1] = pl[(rowA + 8) * LS32 + col];
            aq[1][kk][2] = pl[rowA * LS32 + col + 4];
            aq[1][kk][3] = pl[(rowA + 8) * LS32 + col + 4];
        }
    }

    float o[8][4] = {};
    float m0 = -INFINITY, m1 = -INFINITY, l0 = 0.f, l1 = 0.f;

    for (int j0 = 0; j0 < N; j0 += 64) {
        __syncthreads();
        for (int u = tid; u < 512; u += 128) {
            int r = u >> 3, ch = u & 7;
            ((uint4*)(sKh + r * LSTRIDE))[ch] = ((const uint4*)(g_khi[which] + (size_t)(j0 + r) * D))[ch];
            ((uint4*)(sKl + r * LSTRIDE))[ch] = ((const uint4*)(g_klo[which] + (size_t)(j0 + r) * D))[ch];
            ((uint4*)(sVh + r * LSTRIDE))[ch] = ((const uint4*)(g_vthi[which] + (size_t)r * N + j0))[ch];
            ((uint4*)(sVl + r * LSTRIDE))[ch] = ((const uint4*)(g_vtlo[which] + (size_t)r * N + j0))[ch];
        }
        __syncthreads();

        // ---- S = Q K^T (4 split passes) ----
        float sc[8][4] = {};
        const uint32_t* kh = (const uint32_t*)sKh;
        const uint32_t* kl = (const uint32_t*)sKl;
#pragma unroll
        for (int nt = 0; nt < 8; nt++) {
            uint32_t bh[4][2], bl[4][2];
            int rb = (nt * 8 + q) * LS32;
#pragma unroll
            for (int kk = 0; kk < 4; kk++) {
                bh[kk][0] = kh[rb + kk * 8 + c];
                bh[kk][1] = kh[rb + kk * 8 + c + 4];
                bl[kk][0] = kl[rb + kk * 8 + c];
                bl[kk][1] = kl[rb + kk * 8 + c + 4];
            }
#pragma unroll
            for (int kk = 0; kk < 4; kk++) mma16816(sc[nt], aq[0][kk], bh[kk]);
#pragma unroll
            for (int kk = 0; kk < 4; kk++) mma16816(sc[nt], aq[0][kk], bl[kk]);
#pragma unroll
            for (int kk = 0; kk < 4; kk++) mma16816(sc[nt], aq[1][kk], bh[kk]);
#pragma unroll
            for (int kk = 0; kk < 4; kk++) mma16816(sc[nt], aq[1][kk], bl[kk]);
        }

        // ---- online softmax ----
        float mx0 = -INFINITY, mx1 = -INFINITY;
#pragma unroll
        for (int nt = 0; nt < 8; nt++) {
            mx0 = fmaxf(mx0, fmaxf(sc[nt][0], sc[nt][1]));
            mx1 = fmaxf(mx1, fmaxf(sc[nt][2], sc[nt][3]));
        }
        mx0 = fmaxf(mx0, __shfl_xor_sync(0xffffffffu, mx0, 1));
        mx0 = fmaxf(mx0, __shfl_xor_sync(0xffffffffu, mx0, 2));
        mx1 = fmaxf(mx1, __shfl_xor_sync(0xffffffffu, mx1, 1));
        mx1 = fmaxf(mx1, __shfl_xor_sync(0xffffffffu, mx1, 2));
        float m0n = fmaxf(m0, mx0), m1n = fmaxf(m1, mx1);
        float f0 = __expf(SCALE * (m0 - m0n));
        float f1 = __expf(SCALE * (m1 - m1n));
        m0 = m0n; m1 = m1n;
        l0 *= f0; l1 *= f1;

        uint32_t pah[8], pbh[8], pal[8], pbl[8];
#pragma unroll
        for (int nt = 0; nt < 8; nt++) {
            float p0 = __expf(SCALE * (sc[nt][0] - m0));
            float p1 = __expf(SCALE * (sc[nt][1] - m0));
            float p2 = __expf(SCALE * (sc[nt][2] - m1));
            float p3 = __expf(SCALE * (sc[nt][3] - m1));
            l0 += p0 + p1; l1 += p2 + p3;
            uint32_t h = pack_bf16x2(p0, p1);
            pah[nt] = h;
            pal[nt] = pack_bf16x2(p0 - lo_bf16(h), p1 - hi_bf16(h));
            h = pack_bf16x2(p2, p3);
            pbh[nt] = h;
            pbl[nt] = pack_bf16x2(p2 - lo_bf16(h), p3 - hi_bf16(h));
            o[nt][0] *= f0; o[nt][1] *= f0; o[nt][2] *= f1; o[nt][3] *= f1;
        }

        // ---- O += P V (3 split passes) ----
        const uint32_t* vh = (const uint32_t*)sVh;
        const uint32_t* vl = (const uint32_t*)sVl;
#pragma unroll
        for (int nt = 0; nt < 8; nt++) {
            int rb = (nt * 8 + q) * LS32;
            uint32_t vbh[4][2], vbl[4][2];
#pragma unroll
            for (int kk = 0; kk < 4; kk++) {
                vbh[kk][0] = vh[rb + kk * 8 + c];
                vbh[kk][1] = vh[rb + kk * 8 + c + 4];
                vbl[kk][0] = vl[rb + kk * 8 + c];
                vbl[kk][1] = vl[rb + kk * 8 + c + 4];
            }
#pragma unroll
            for (int kk = 0; kk < 4; kk++) {
                uint32_t Ah[4] = {pah[2 * kk], pbh[2 * kk], pah[2 * kk + 1], pbh[2 * kk + 1]};
                uint32_t Al[4] = {pal[2 * kk], pbl[2 * kk], pal[2 * kk + 1], pbl[2 * kk + 1]};
                mma16816(o[nt], Ah, vbh[kk]);
                mma16816(o[nt], Ah, vbl[kk]);
                mma16816(o[nt], Al, vbh[kk]);
            }
        }
    }

    // ---- epilogue: normalize, norms, store split att ----
    l0 += __shfl_xor_sync(0xffffffffu, l0, 1);
    l0 += __shfl_xor_sync(0xffffffffu, l0, 2);
    l1 += __shfl_xor_sync(0xffffffffu, l1, 1);
    l1 += __shfl_xor_sync(0xffffffffu, l1, 2);
    float inv0 = 1.0f / l0, inv1 = 1.0f / l1;
    float n0 = 0.f, n1 = 0.f;
    int row = q0 + rowA;
    uint32_t* dh = (uint32_t*)g_atthi[which];
    uint32_t* dl = (uint32_t*)g_attlo[which];
#pragma unroll
    for (int nt = 0; nt < 8; nt++) {
        float o0 = o[nt][0] * inv0, o1 = o[nt][1] * inv0;
        float o2 = o[nt][2] * inv1, o3 = o[nt][3] * inv1;
        n0 = fmaf(o0, o0, fmaf(o1, o1, n0));
        n1 = fmaf(o2, o2, fmaf(o3, o3, n1));
        uint32_t h = pack_bf16x2(o0, o1);
        dh[(size_t)row * 32 + nt * 4 + c] = h;
        dl[(size_t)row * 32 + nt * 4 + c] = pack_bf16x2(o0 - lo_bf16(h), o1 - hi_bf16(h));
        h = pack_bf16x2(o2, o3);
        dh[(size_t)(row + 8) * 32 + nt * 4 + c] = h;
        dl[(size_t)(row + 8) * 32 + nt * 4 + c] = pack_bf16x2(o2 - lo_bf16(h), o3 - hi_bf16(h));
    }
    n0 += __shfl_xor_sync(0xffffffffu, n0, 1);
    n0 += __shfl_xor_sync(0xffffffffu, n0, 2);
    n1 += __shfl_xor_sync(0xffffffffu, n1, 1);
    n1 += __shfl_xor_sync(0xffffffffu, n1, 2);
    if (c == 0) {
        g_norm2[which][row] = n0;
        g_norm2[which][row + 8] = n1;
    }
}

// ---------------------------------------------------------------------------
// kernel 3: pairwise RBF via mma.sync (64x64 tile per CTA, 4-pass split)
// ---------------------------------------------------------------------------
__global__ __launch_bounds__(128, 2) void pairwise_mma_kernel(float* __restrict__ out) {
    __shared__ __nv_bfloat16 sAh[64 * LSTRIDE];
    __shared__ __nv_bfloat16 sAl[64 * LSTRIDE];
    __shared__ __nv_bfloat16 sBh[64 * LSTRIDE];
    __shared__ __nv_bfloat16 sBl[64 * LSTRIDE];
    __shared__ float syn[64];

    int tid = threadIdx.x;
    int w = tid >> 5, lane = tid & 31;
    int q = lane >> 2, c = lane & 3;
    int m0 = blockIdx.y * 64;
    int j0 = blockIdx.x * 64;
    int rowA = w * 16 + q;

    for (int u = tid; u < 512; u += 128) {
        int r = u >> 3, ch = u & 7;
        ((uint4*)(sAh + r * LSTRIDE))[ch] = ((const uint4*)(g_atthi[0] + (size_t)(m0 + r) * D))[ch];
        ((uint4*)(sAl + r * LSTRIDE))[ch] = ((const uint4*)(g_attlo[0] + (size_t)(m0 + r) * D))[ch];
        ((uint4*)(sBh + r * LSTRIDE))[ch] = ((const uint4*)(g_atthi[1] + (size_t)(j0 + r) * D))[ch];
        ((uint4*)(sBl + r * LSTRIDE))[ch] = ((const uint4*)(g_attlo[1] + (size_t)(j0 + r) * D))[ch];
    }
    if (tid < 64) syn[tid] = g_norm2[1][j0 + tid];
    __syncthreads();

    uint32_t aq[2][4][4];
    {
        const uint32_t* ph = (const uint32_t*)sAh;
        const uint32_t* pl = (const uint32_t*)sAl;
#pragma unroll
        for (int kk = 0; kk < 4; kk++) {
            int col = kk * 8 + c;
            aq[0][kk][0] = ph[rowA * LS32 + col];
            aq[0][kk][1] = ph[(rowA + 8) * LS32 + col];
            aq[0][kk][2] = ph[rowA * LS32 + col + 4];
            aq[0][kk][3] = ph[(rowA + 8) * LS32 + col + 4];
            aq[1][kk][0] = pl[rowA * LS32 + col];
            aq[1][kk][1] = pl[(rowA + 8) * LS32 + col];
            aq[1][kk][2] = pl[rowA * LS32 + col + 4];
            aq[1][kk][3] = pl[(rowA + 8) * LS32 + col + 4];
        }
    }

    float acc[8][4] = {};
    const uint32_t* bhp = (const uint32_t*)sBh;
    const uint32_t* blp = (const uint32_t*)sBl;
#pragma unroll
    for (int nt = 0; nt < 8; nt++) {
        uint32_t bh[4][2], bl[4][2];
        int rb = (nt * 8 + q) * LS32;
#pragma unroll
        for (int kk = 0; kk < 4; kk++) {
            bh[kk][0] = bhp[rb + kk * 8 + c];
            bh[kk][1] = bhp[rb + kk * 8 + c + 4];
            bl[kk][0] = blp[rb + kk * 8 + c];
            bl[kk][1] = blp[rb + kk * 8 + c + 4];
        }
#pragma unroll
        for (int kk = 0; kk < 4; kk++) mma16816(acc[nt], aq[0][kk], bh[kk]);
#pragma unroll
        for (int kk = 0; kk < 4; kk++) mma16816(acc[nt], aq[0][kk], bl[kk]);
#pragma unroll
        for (int kk = 0; kk < 4; kk++) mma16816(acc[nt], aq[1][kk], bh[kk]);
#pragma unroll
        for (int kk = 0; kk < 4; kk++) mma16816(acc[nt], aq[1][kk], bl[kk]);
    }

    int rowx = m0 + rowA;
    float xn0 = g_norm2[0][rowx];
    float xn1 = g_norm2[0][rowx + 8];
#pragma unroll
    for (int nt = 0; nt < 8; nt++) {
        int cb = nt * 8 + 2 * c;
        float y0 = syn[cb], y1 = syn[cb + 1];
        float2 e;
        e.x = __expf(-(xn0 + y0 - 2.f * acc[nt][0]));
        e.y = __expf(-(xn0 + y1 - 2.f * acc[nt][1]));
        *reinterpret_cast<float2*>(out + (size_t)rowx * N + j0 + cb) = e;
        e.x = __expf(-(xn1 + y0 - 2.f * acc[nt][2]));
        e.y = __expf(-(xn1 + y1 - 2.f * acc[nt][3]));
        *reinterpret_cast<float2*>(out + (size_t)(rowx + 8) * N + j0 + cb) = e;
    }
}

// ---------------------------------------------------------------------------
extern "C" void kernel_launch(void* const* d_in, const int* in_sizes, int n_in,
                              void* d_out, int out_size) {
    const float* Wq = (const float*)d_in[0];
    const float* Wk = (const float*)d_in[1];
    const float* x  = (const float*)d_in[2];
    const float* y  = (const float*)d_in[3];
    float* out = (float*)d_out;

    prep_kernel<<<2 * N / 4, 256>>>(x, y, Wq, Wk);
    flash_mma_kernel<<<256, 128>>>();
    dim3 grid(N / 64, N / 64);
    pairwise_mma_kernel<<<grid, 128>>>(out);
}

// round 6
// speedup vs baseline: 4.6159x; 1.2510x over previous
#include <cuda_runtime.h>
#include <cuda_bf16.h>
#include <cstdint>
#include <math.h>

#define N 8192
#define D 64
#define SCALE 0.125f      // 1/sqrt(64)
#define LSTRIDE 72        // smem row stride in bf16 (144B, conflict-free)
#define LS32 36           // row stride in u32 words
#define RB 144            // row stride in bytes

// ---------------------------------------------------------------------------
// global scratch (no allocation allowed)
// ---------------------------------------------------------------------------
__device__ __nv_bfloat16 g_qhi[2][N * D];
__device__ __nv_bfloat16 g_qlo[2][N * D];
__device__ __nv_bfloat16 g_khi[2][N * D];
__device__ __nv_bfloat16 g_klo[2][N * D];
__device__ __nv_bfloat16 g_vthi[2][D * N];   // V^T: [d][n]
__device__ __nv_bfloat16 g_vtlo[2][D * N];
__device__ __nv_bfloat16 g_atthi[2][N * D];
__device__ __nv_bfloat16 g_attlo[2][N * D];
__device__ float g_norm2[2][N];

// ---------------------------------------------------------------------------
// helpers
// ---------------------------------------------------------------------------
__device__ __forceinline__ uint32_t smem_u32(const void* p) {
    uint32_t a;
    asm("{ .reg .u64 t; cvta.to.shared.u64 t, %1; cvt.u32.u64 %0, t; }" : "=r"(a) : "l"(p));
    return a;
}
__device__ __forceinline__ void mma16816(float* c, const uint32_t* a, const uint32_t* b) {
    asm volatile(
        "mma.sync.aligned.m16n8k16.row.col.f32.bf16.bf16.f32 "
        "{%0,%1,%2,%3}, {%4,%5,%6,%7}, {%8,%9}, {%0,%1,%2,%3};\n"
        : "+f"(c[0]), "+f"(c[1]), "+f"(c[2]), "+f"(c[3])
        : "r"(a[0]), "r"(a[1]), "r"(a[2]), "r"(a[3]), "r"(b[0]), "r"(b[1]));
}
__device__ __forceinline__ void ldmx4(uint32_t* r, uint32_t saddr) {
    asm volatile("ldmatrix.sync.aligned.m8n8.x4.shared.b16 {%0,%1,%2,%3}, [%4];"
        : "=r"(r[0]), "=r"(r[1]), "=r"(r[2]), "=r"(r[3]) : "r"(saddr));
}
__device__ __forceinline__ void cp16(uint32_t saddr, const void* gaddr) {
    asm volatile("cp.async.cg.shared.global [%0], [%1], 16;" :: "r"(saddr), "l"(gaddr));
}
#define CP_COMMIT() asm volatile("cp.async.commit_group;" ::: "memory")
template <int n>
__device__ __forceinline__ void cp_wait() {
    asm volatile("cp.async.wait_group %0;" :: "n"(n) : "memory");
}
__device__ __forceinline__ uint32_t pack_bf16x2(float lo, float hi) {
    uint32_t r;
    asm("cvt.rn.bf16x2.f32 %0, %1, %2;" : "=r"(r) : "f"(hi), "f"(lo));
    return r;
}
__device__ __forceinline__ float lo_bf16(uint32_t p) { return __uint_as_float(p << 16); }
__device__ __forceinline__ float hi_bf16(uint32_t p) { return __uint_as_float(p & 0xFFFF0000u); }
__device__ __forceinline__ void split2(float v, __nv_bfloat16& h, __nv_bfloat16& l) {
    h = __float2bfloat16(v);
    l = __float2bfloat16(v - __bfloat162float(h));
}

// ---------------------------------------------------------------------------
// kernel 1: Q/K projection + bf16 splits + transposed V splits
// 256 blocks, 64 rows/block -> W read once per block (8MB L2 total).
// ---------------------------------------------------------------------------
__global__ __launch_bounds__(256) void prep_kernel(const float* __restrict__ x,
                                                   const float* __restrict__ y,
                                                   const float* __restrict__ Wq,
                                                   const float* __restrict__ Wk) {
    __shared__ float sWq[D * D];
    __shared__ float sWk[D * D];
    __shared__ float sIn[64][D];
    int tid = threadIdx.x;
    int b = blockIdx.x;
    int which = (b >= 128) ? 1 : 0;
    const float* in = which ? y : x;
    int row0 = (b & 127) * 64;

    for (int i = tid; i < D * D; i += 256) { sWq[i] = Wq[i]; sWk[i] = Wk[i]; }
    for (int u = tid; u < 64 * D; u += 256)
        sIn[u >> 6][u & 63] = in[(size_t)(row0 + (u >> 6)) * D + (u & 63)];
    __syncthreads();

    int c = tid & 63, rq = tid >> 6;
#pragma unroll 4
    for (int i = 0; i < 16; i++) {
        int r = rq * 16 + i;
        float aq = 0.f, ak = 0.f;
#pragma unroll
        for (int k = 0; k < D; k++) {
            float v = sIn[r][k];
            aq = fmaf(v, sWq[k * D + c], aq);
            ak = fmaf(v, sWk[k * D + c], ak);
        }
        int n = row0 + r;
        __nv_bfloat16 h, l;
        split2(aq, h, l); g_qhi[which][(size_t)n * D + c] = h; g_qlo[which][(size_t)n * D + c] = l;
        split2(ak, h, l); g_khi[which][(size_t)n * D + c] = h; g_klo[which][(size_t)n * D + c] = l;
        split2(sIn[r][c], h, l);
        g_vthi[which][(size_t)c * N + n] = h; g_vtlo[which][(size_t)c * N + n] = l;
    }
}

// ---------------------------------------------------------------------------
// kernel 2: single-pass flash attention, double-buffered cp.async + ldmatrix
// CTA: 128 threads (4 warps), 64 query rows, 64-key tiles, 128 iterations.
// ---------------------------------------------------------------------------
#define TILE_B 36864   // bytes per buffer: 4 arrays x 64 rows x 144B
#define OFF_KH 0
#define OFF_KL 9216
#define OFF_VH 18432
#define OFF_VL 27648
#define SMEM_FLASH (2 * TILE_B)

__device__ __forceinline__ void flash_issue_tile(uint32_t sbu, char* smf, int buf,
                                                 int which, int j0, int tid) {
    uint32_t bo = sbu + buf * TILE_B;
#pragma unroll
    for (int u = tid; u < 512; u += 128) {
        int r = u >> 3, ch = u & 7;
        uint32_t so = (uint32_t)r * RB + (uint32_t)ch * 16;
        cp16(bo + OFF_KH + so, g_khi[which] + (size_t)(j0 + r) * D + ch * 8);
        cp16(bo + OFF_KL + so, g_klo[which] + (size_t)(j0 + r) * D + ch * 8);
        cp16(bo + OFF_VH + so, g_vthi[which] + (size_t)r * N + j0 + ch * 8);
        cp16(bo + OFF_VL + so, g_vtlo[which] + (size_t)r * N + j0 + ch * 8);
    }
    CP_COMMIT();
}

__global__ __launch_bounds__(128, 2) void flash_mma_kernel() {
    extern __shared__ char smf[];
    uint32_t sbu = smem_u32(smf);

    int tid = threadIdx.x;
    int w = tid >> 5, lane = tid & 31;
    int q = lane >> 2, c = lane & 3;
    int which = blockIdx.x >> 7;
    int q0 = (blockIdx.x & 127) * 64;
    int rowA = w * 16 + q;

    // stage Q tile into buf0 (plain loads), extract A fragments, then release buf0
    for (int u = tid; u < 512; u += 128) {
        int r = u >> 3, ch = u & 7;
        *(uint4*)(smf + OFF_KH + r * RB + ch * 16) =
            ((const uint4*)(g_qhi[which] + (size_t)(q0 + r) * D))[ch];
        *(uint4*)(smf + OFF_KL + r * RB + ch * 16) =
            ((const uint4*)(g_qlo[which] + (size_t)(q0 + r) * D))[ch];
    }
    __syncthreads();

    uint32_t aq[2][4][4];
    {
        const uint32_t* ph = (const uint32_t*)(smf + OFF_KH);
        const uint32_t* pl = (const uint32_t*)(smf + OFF_KL);
#pragma unroll
        for (int kk = 0; kk < 4; kk++) {
            int col = kk * 8 + c;
            aq[0][kk][0] = ph[rowA * LS32 + col];
            aq[0][kk][1] = ph[(rowA + 8) * LS32 + col];
            aq[0][kk][2] = ph[rowA * LS32 + col + 4];
            aq[0][kk][3] = ph[(rowA + 8) * LS32 + col + 4];
            aq[1][kk][0] = pl[rowA * LS32 + col];
            aq[1][kk][1] = pl[(rowA + 8) * LS32 + col];
            aq[1][kk][2] = pl[rowA * LS32 + col + 4];
            aq[1][kk][3] = pl[(rowA + 8) * LS32 + col + 4];
        }
    }
    __syncthreads();

    // prologue: prefetch tile 0
    flash_issue_tile(sbu, smf, 0, which, 0, tid);

    float o[8][4] = {};
    float m0 = -INFINITY, m1 = -INFINITY, l0 = 0.f, l1 = 0.f;
    uint32_t lmoff = (uint32_t)(lane & 7) * RB + (uint32_t)(lane >> 3) * 16;

    for (int t = 0; t < 128; t++) {
        if (t < 127) flash_issue_tile(sbu, smf, (t + 1) & 1, which, (t + 1) * 64, tid);
        if (t < 127) cp_wait<1>(); else cp_wait<0>();
        __syncthreads();
        uint32_t bufb = sbu + (t & 1) * TILE_B;

        // ---- S = Q K^T (3 split passes: hh, hl, lh) ----
        float sc[8][4] = {};
#pragma unroll
        for (int nt = 0; nt < 8; nt++) {
            uint32_t a0 = bufb + (uint32_t)nt * (8 * RB) + lmoff;
            uint32_t bh[4][2], bl[4][2];
            ldmx4(&bh[0][0], a0 + OFF_KH);
            ldmx4(&bh[2][0], a0 + OFF_KH + 64);
            ldmx4(&bl[0][0], a0 + OFF_KL);
            ldmx4(&bl[2][0], a0 + OFF_KL + 64);
#pragma unroll
            for (int kk = 0; kk < 4; kk++) mma16816(sc[nt], aq[0][kk], bh[kk]);
#pragma unroll
            for (int kk = 0; kk < 4; kk++) mma16816(sc[nt], aq[0][kk], bl[kk]);
#pragma unroll
            for (int kk = 0; kk < 4; kk++) mma16816(sc[nt], aq[1][kk], bh[kk]);
        }

        // ---- online softmax ----
        float mx0 = -INFINITY, mx1 = -INFINITY;
#pragma unroll
        for (int nt = 0; nt < 8; nt++) {
            mx0 = fmaxf(mx0, fmaxf(sc[nt][0], sc[nt][1]));
            mx1 = fmaxf(mx1, fmaxf(sc[nt][2], sc[nt][3]));
        }
        mx0 = fmaxf(mx0, __shfl_xor_sync(0xffffffffu, mx0, 1));
        mx0 = fmaxf(mx0, __shfl_xor_sync(0xffffffffu, mx0, 2));
        mx1 = fmaxf(mx1, __shfl_xor_sync(0xffffffffu, mx1, 1));
        mx1 = fmaxf(mx1, __shfl_xor_sync(0xffffffffu, mx1, 2));
        float m0n = fmaxf(m0, mx0), m1n = fmaxf(m1, mx1);
        float f0 = __expf(SCALE * (m0 - m0n));
        float f1 = __expf(SCALE * (m1 - m1n));
        m0 = m0n; m1 = m1n;
        l0 *= f0; l1 *= f1;

        uint32_t pah[8], pbh[8], pal[8], pbl[8];
#pragma unroll
        for (int nt = 0; nt < 8; nt++) {
            float p0 = __expf(SCALE * (sc[nt][0] - m0));
            float p1 = __expf(SCALE * (sc[nt][1] - m0));
            float p2 = __expf(SCALE * (sc[nt][2] - m1));
            float p3 = __expf(SCALE * (sc[nt][3] - m1));
            l0 += p0 + p1; l1 += p2 + p3;
            uint32_t h = pack_bf16x2(p0, p1);
            pah[nt] = h;
            pal[nt] = pack_bf16x2(p0 - lo_bf16(h), p1 - hi_bf16(h));
            h = pack_bf16x2(p2, p3);
            pbh[nt] = h;
            pbl[nt] = pack_bf16x2(p2 - lo_bf16(h), p3 - hi_bf16(h));
            o[nt][0] *= f0; o[nt][1] *= f0; o[nt][2] *= f1; o[nt][3] *= f1;
        }

        // ---- O += P V (3 split passes) ----
#pragma unroll
        for (int nt = 0; nt < 8; nt++) {
            uint32_t a0 = bufb + (uint32_t)nt * (8 * RB) + lmoff;
            uint32_t vbh[4][2], vbl[4][2];
            ldmx4(&vbh[0][0], a0 + OFF_VH);
            ldmx4(&vbh[2][0], a0 + OFF_VH + 64);
            ldmx4(&vbl[0][0], a0 + OFF_VL);
            ldmx4(&vbl[2][0], a0 + OFF_VL + 64);
#pragma unroll
            for (int kk = 0; kk < 4; kk++) {
                uint32_t Ah[4] = {pah[2 * kk], pbh[2 * kk], pah[2 * kk + 1], pbh[2 * kk + 1]};
                uint32_t Al[4] = {pal[2 * kk], pbl[2 * kk], pal[2 * kk + 1], pbl[2 * kk + 1]};
                mma16816(o[nt], Ah, vbh[kk]);
                mma16816(o[nt], Ah, vbl[kk]);
                mma16816(o[nt], Al, vbh[kk]);
            }
        }
        __syncthreads();
    }

    // ---- epilogue ----
    l0 += __shfl_xor_sync(0xffffffffu, l0, 1);
    l0 += __shfl_xor_sync(0xffffffffu, l0, 2);
    l1 += __shfl_xor_sync(0xffffffffu, l1, 1);
    l1 += __shfl_xor_sync(0xffffffffu, l1, 2);
    float inv0 = 1.0f / l0, inv1 = 1.0f / l1;
    float n0 = 0.f, n1 = 0.f;
    int row = q0 + rowA;
    uint32_t* dh = (uint32_t*)g_atthi[which];
    uint32_t* dl = (uint32_t*)g_attlo[which];
#pragma unroll
    for (int nt = 0; nt < 8; nt++) {
        float o0 = o[nt][0] * inv0, o1 = o[nt][1] * inv0;
        float o2 = o[nt][2] * inv1, o3 = o[nt][3] * inv1;
        n0 = fmaf(o0, o0, fmaf(o1, o1, n0));
        n1 = fmaf(o2, o2, fmaf(o3, o3, n1));
        uint32_t h = pack_bf16x2(o0, o1);
        dh[(size_t)row * 32 + nt * 4 + c] = h;
        dl[(size_t)row * 32 + nt * 4 + c] = pack_bf16x2(o0 - lo_bf16(h), o1 - hi_bf16(h));
        h = pack_bf16x2(o2, o3);
        dh[(size_t)(row + 8) * 32 + nt * 4 + c] = h;
        dl[(size_t)(row + 8) * 32 + nt * 4 + c] = pack_bf16x2(o2 - lo_bf16(h), o3 - hi_bf16(h));
    }
    n0 += __shfl_xor_sync(0xffffffffu, n0, 1);
    n0 += __shfl_xor_sync(0xffffffffu, n0, 2);
    n1 += __shfl_xor_sync(0xffffffffu, n1, 1);
    n1 += __shfl_xor_sync(0xffffffffu, n1, 2);
    if (c == 0) {
        g_norm2[which][row] = n0;
        g_norm2[which][row + 8] = n1;
    }
}

// ---------------------------------------------------------------------------
// kernel 3: pairwise RBF via mma.sync (64x64 tile, 4-pass split, ldmatrix)
// ---------------------------------------------------------------------------
__global__ __launch_bounds__(128, 3) void pairwise_mma_kernel(float* __restrict__ out) {
    __shared__ __nv_bfloat16 sAh[64 * LSTRIDE];
    __shared__ __nv_bfloat16 sAl[64 * LSTRIDE];
    __shared__ __nv_bfloat16 sBh[64 * LSTRIDE];
    __shared__ __nv_bfloat16 sBl[64 * LSTRIDE];
    __shared__ float syn[64];

    int tid = threadIdx.x;
    int w = tid >> 5, lane = tid & 31;
    int q = lane >> 2, c = lane & 3;
    int m0 = blockIdx.y * 64;
    int j0 = blockIdx.x * 64;
    int rowA = w * 16 + q;

    for (int u = tid; u < 512; u += 128) {
        int r = u >> 3, ch = u & 7;
        ((uint4*)(sAh + r * LSTRIDE))[ch] = ((const uint4*)(g_atthi[0] + (size_t)(m0 + r) * D))[ch];
        ((uint4*)(sAl + r * LSTRIDE))[ch] = ((const uint4*)(g_attlo[0] + (size_t)(m0 + r) * D))[ch];
        ((uint4*)(sBh + r * LSTRIDE))[ch] = ((const uint4*)(g_atthi[1] + (size_t)(j0 + r) * D))[ch];
        ((uint4*)(sBl + r * LSTRIDE))[ch] = ((const uint4*)(g_attlo[1] + (size_t)(j0 + r) * D))[ch];
    }
    if (tid < 64) syn[tid] = g_norm2[1][j0 + tid];
    __syncthreads();

    uint32_t aq[2][4][4];
    {
        const uint32_t* ph = (const uint32_t*)sAh;
        const uint32_t* pl = (const uint32_t*)sAl;
#pragma unroll
        for (int kk = 0; kk < 4; kk++) {
            int col = kk * 8 + c;
            aq[0][kk][0] = ph[rowA * LS32 + col];
            aq[0][kk][1] = ph[(rowA + 8) * LS32 + col];
            aq[0][kk][2] = ph[rowA * LS32 + col + 4];
            aq[0][kk][3] = ph[(rowA + 8) * LS32 + col + 4];
            aq[1][kk][0] = pl[rowA * LS32 + col];
            aq[1][kk][1] = pl[(rowA + 8) * LS32 + col];
            aq[1][kk][2] = pl[rowA * LS32 + col + 4];
            aq[1][kk][3] = pl[(rowA + 8) * LS32 + col + 4];
        }
    }

    uint32_t sbh = smem_u32(sBh), sbl = smem_u32(sBl);
    uint32_t lmoff = (uint32_t)(lane & 7) * RB + (uint32_t)(lane >> 3) * 16;
    float acc[8][4] = {};
#pragma unroll
    for (int nt = 0; nt < 8; nt++) {
        uint32_t ro = (uint32_t)nt * (8 * RB) + lmoff;
        uint32_t bh[4][2], bl[4][2];
        ldmx4(&bh[0][0], sbh + ro);
        ldmx4(&bh[2][0], sbh + ro + 64);
        ldmx4(&bl[0][0], sbl + ro);
        ldmx4(&bl[2][0], sbl + ro + 64);
#pragma unroll
        for (int kk = 0; kk < 4; kk++) mma16816(acc[nt], aq[0][kk], bh[kk]);
#pragma unroll
        for (int kk = 0; kk < 4; kk++) mma16816(acc[nt], aq[0][kk], bl[kk]);
#pragma unroll
        for (int kk = 0; kk < 4; kk++) mma16816(acc[nt], aq[1][kk], bh[kk]);
#pragma unroll
        for (int kk = 0; kk < 4; kk++) mma16816(acc[nt], aq[1][kk], bl[kk]);
    }

    int rowx = m0 + rowA;
    float xn0 = g_norm2[0][rowx];
    float xn1 = g_norm2[0][rowx + 8];
#pragma unroll
    for (int nt = 0; nt < 8; nt++) {
        int cb = nt * 8 + 2 * c;
        float y0 = syn[cb], y1 = syn[cb + 1];
        float2 e;
        e.x = __expf(-(xn0 + y0 - 2.f * acc[nt][0]));
        e.y = __expf(-(xn0 + y1 - 2.f * acc[nt][1]));
        *reinterpret_cast<float2*>(out + (size_t)rowx * N + j0 + cb) = e;
        e.x = __expf(-(xn1 + y0 - 2.f * acc[nt][2]));
        e.y = __expf(-(xn1 + y1 - 2.f * acc[nt][3]));
        *reinterpret_cast<float2*>(out + (size_t)(rowx + 8) * N + j0 + cb) = e;
    }
}

// ---------------------------------------------------------------------------
extern "C" void kernel_launch(void* const* d_in, const int* in_sizes, int n_in,
                              void* d_out, int out_size) {
    const float* Wq = (const float*)d_in[0];
    const float* Wk = (const float*)d_in[1];
    const float* x  = (const float*)d_in[2];
    const float* y  = (const float*)d_in[3];
    float* out = (float*)d_out;

    prep_kernel<<<256, 256>>>(x, y, Wq, Wk);

    cudaFuncSetAttribute(flash_mma_kernel, cudaFuncAttributeMaxDynamicSharedMemorySize,
                         SMEM_FLASH);
    flash_mma_kernel<<<256, 128, SMEM_FLASH>>>();

    dim3 grid(N / 64, N / 64);
    pairwise_mma_kernel<<<grid, 128>>>(out);
}

// round 7
// speedup vs baseline: 4.8953x; 1.0605x over previous
#include <cuda_runtime.h>
#include <cuda_bf16.h>
#include <cstdint>
#include <math.h>

#define N 8192
#define D 64
#define SCALE 0.125f      // 1/sqrt(64)
#define LSTRIDE 72        // smem row stride in bf16 (144B, conflict-free)
#define LS32 36           // row stride in u32 words
#define RB 144            // row stride in bytes

// ---------------------------------------------------------------------------
// global scratch (no allocation allowed) -- all row-major [n][64] bf16 splits
// ---------------------------------------------------------------------------
__device__ __nv_bfloat16 g_qhi[2][N * D];
__device__ __nv_bfloat16 g_qlo[2][N * D];
__device__ __nv_bfloat16 g_khi[2][N * D];
__device__ __nv_bfloat16 g_klo[2][N * D];
__device__ __nv_bfloat16 g_vhi[2][N * D];    // V (inputs) split, row-major
__device__ __nv_bfloat16 g_vlo[2][N * D];
__device__ __nv_bfloat16 g_atthi[2][N * D];
__device__ __nv_bfloat16 g_attlo[2][N * D];
__device__ float g_norm2[2][N];

// ---------------------------------------------------------------------------
// helpers
// ---------------------------------------------------------------------------
__device__ __forceinline__ uint32_t smem_u32(const void* p) {
    uint32_t a;
    asm("{ .reg .u64 t; cvta.to.shared.u64 t, %1; cvt.u32.u64 %0, t; }" : "=r"(a) : "l"(p));
    return a;
}
__device__ __forceinline__ void mma16816(float* c, const uint32_t* a, const uint32_t* b) {
    asm volatile(
        "mma.sync.aligned.m16n8k16.row.col.f32.bf16.bf16.f32 "
        "{%0,%1,%2,%3}, {%4,%5,%6,%7}, {%8,%9}, {%0,%1,%2,%3};\n"
        : "+f"(c[0]), "+f"(c[1]), "+f"(c[2]), "+f"(c[3])
        : "r"(a[0]), "r"(a[1]), "r"(a[2]), "r"(a[3]), "r"(b[0]), "r"(b[1]));
}
__device__ __forceinline__ void ldmx4(uint32_t* r, uint32_t saddr) {
    asm volatile("ldmatrix.sync.aligned.m8n8.x4.shared.b16 {%0,%1,%2,%3}, [%4];"
        : "=r"(r[0]), "=r"(r[1]), "=r"(r[2]), "=r"(r[3]) : "r"(saddr));
}
__device__ __forceinline__ void ldmx4t(uint32_t* r, uint32_t saddr) {
    asm volatile("ldmatrix.sync.aligned.m8n8.x4.trans.shared.b16 {%0,%1,%2,%3}, [%4];"
        : "=r"(r[0]), "=r"(r[1]), "=r"(r[2]), "=r"(r[3]) : "r"(saddr));
}
__device__ __forceinline__ void cp16(uint32_t saddr, const void* gaddr) {
    asm volatile("cp.async.cg.shared.global [%0], [%1], 16;" :: "r"(saddr), "l"(gaddr));
}
#define CP_COMMIT() asm volatile("cp.async.commit_group;" ::: "memory")
template <int n>
__device__ __forceinline__ void cp_wait() {
    asm volatile("cp.async.wait_group %0;" :: "n"(n) : "memory");
}
__device__ __forceinline__ uint32_t pack_bf16x2(float lo, float hi) {
    uint32_t r;
    asm("cvt.rn.bf16x2.f32 %0, %1, %2;" : "=r"(r) : "f"(hi), "f"(lo));
    return r;
}
__device__ __forceinline__ float lo_bf16(uint32_t p) { return __uint_as_float(p << 16); }
__device__ __forceinline__ float hi_bf16(uint32_t p) { return __uint_as_float(p & 0xFFFF0000u); }

// ---------------------------------------------------------------------------
// kernel 1: Q/K projection + bf16 splits, all row-major coalesced bf16x2 writes
// 256 blocks x 256 threads, 64 rows/block, 2x2 micro-tile.
// ---------------------------------------------------------------------------
__global__ __launch_bounds__(256) void prep_kernel(const float* __restrict__ x,
                                                   const float* __restrict__ y,
                                                   const float* __restrict__ Wq,
                                                   const float* __restrict__ Wk) {
    __shared__ float sW[2][D * D];   // 32KB
    __shared__ float sIn[64][D];     // 16KB
    int tid = threadIdx.x;
    int b = blockIdx.x;
    int which = (b >= 128) ? 1 : 0;
    const float* in = which ? y : x;
    int row0 = (b & 127) * 64;

    for (int i = tid; i < D * D; i += 256) { sW[0][i] = Wq[i]; sW[1][i] = Wk[i]; }
    for (int u = tid; u < 64 * D; u += 256)
        ((float*)sIn)[u] = in[(size_t)row0 * D + u];
    __syncthreads();

    int c0 = (tid & 31) * 2;
    int rb = (tid >> 5) * 2;
    uint32_t* qh = (uint32_t*)g_qhi[which];
    uint32_t* ql = (uint32_t*)g_qlo[which];
    uint32_t* kh = (uint32_t*)g_khi[which];
    uint32_t* kl = (uint32_t*)g_klo[which];

#pragma unroll
    for (int p = 0; p < 4; p++) {
        int r = rb + p * 16;
        float aq0 = 0.f, aq1 = 0.f, aq2 = 0.f, aq3 = 0.f;
        float ak0 = 0.f, ak1 = 0.f, ak2 = 0.f, ak3 = 0.f;
#pragma unroll
        for (int k = 0; k < D; k++) {
            float2 wq = *(const float2*)&sW[0][k * D + c0];
            float2 wk = *(const float2*)&sW[1][k * D + c0];
            float i0 = sIn[r][k], i1 = sIn[r + 1][k];
            aq0 = fmaf(i0, wq.x, aq0); aq1 = fmaf(i0, wq.y, aq1);
            aq2 = fmaf(i1, wq.x, aq2); aq3 = fmaf(i1, wq.y, aq3);
            ak0 = fmaf(i0, wk.x, ak0); ak1 = fmaf(i0, wk.y, ak1);
            ak2 = fmaf(i1, wk.x, ak2); ak3 = fmaf(i1, wk.y, ak3);
        }
        size_t i0x = ((size_t)(row0 + r) * D + c0) >> 1;
        size_t i1x = ((size_t)(row0 + r + 1) * D + c0) >> 1;
        uint32_t h;
        h = pack_bf16x2(aq0, aq1); qh[i0x] = h;
        ql[i0x] = pack_bf16x2(aq0 - lo_bf16(h), aq1 - hi_bf16(h));
        h = pack_bf16x2(aq2, aq3); qh[i1x] = h;
        ql[i1x] = pack_bf16x2(aq2 - lo_bf16(h), aq3 - hi_bf16(h));
        h = pack_bf16x2(ak0, ak1); kh[i0x] = h;
        kl[i0x] = pack_bf16x2(ak0 - lo_bf16(h), ak1 - hi_bf16(h));
        h = pack_bf16x2(ak2, ak3); kh[i1x] = h;
        kl[i1x] = pack_bf16x2(ak2 - lo_bf16(h), ak3 - hi_bf16(h));
    }

    // V splits straight from sIn, row-major coalesced
    uint32_t* vh = (uint32_t*)g_vhi[which];
    uint32_t* vl = (uint32_t*)g_vlo[which];
    for (int u = tid; u < 2048; u += 256) {
        int r = u >> 5, cc = (u & 31) * 2;
        float v0 = sIn[r][cc], v1 = sIn[r][cc + 1];
        uint32_t h = pack_bf16x2(v0, v1);
        size_t idx = ((size_t)(row0 + r) * D + cc) >> 1;
        vh[idx] = h;
        vl[idx] = pack_bf16x2(v0 - lo_bf16(h), v1 - hi_bf16(h));
    }
}

// ---------------------------------------------------------------------------
// kernel 2: single-pass flash attention, depth-3 cp.async ring, 1 barrier/iter
// CTA: 128 threads (4 warps), 64 query rows, 64-key tiles, 128 iterations.
// ---------------------------------------------------------------------------
#define TILE_B 36864   // per-buffer: 4 arrays x 64 rows x 144B
#define OFF_KH 0
#define OFF_KL 9216
#define OFF_VH 18432
#define OFF_VL 27648
#define SMEM_FLASH (3 * TILE_B)

__device__ __forceinline__ void flash_issue_tile(uint32_t sbu, int buf,
                                                 int which, int j0, int tid) {
    uint32_t bo = sbu + (uint32_t)buf * TILE_B;
#pragma unroll
    for (int u = tid; u < 512; u += 128) {
        int r = u >> 3, ch = u & 7;
        uint32_t so = (uint32_t)r * RB + (uint32_t)ch * 16;
        cp16(bo + OFF_KH + so, g_khi[which] + (size_t)(j0 + r) * D + ch * 8);
        cp16(bo + OFF_KL + so, g_klo[which] + (size_t)(j0 + r) * D + ch * 8);
        cp16(bo + OFF_VH + so, g_vhi[which] + (size_t)(j0 + r) * D + ch * 8);
        cp16(bo + OFF_VL + so, g_vlo[which] + (size_t)(j0 + r) * D + ch * 8);
    }
    CP_COMMIT();
}

__global__ __launch_bounds__(128, 2) void flash_mma_kernel() {
    extern __shared__ char smf[];
    uint32_t sbu = smem_u32(smf);

    int tid = threadIdx.x;
    int w = tid >> 5, lane = tid & 31;
    int q = lane >> 2, c = lane & 3;
    int which = blockIdx.x >> 7;
    int q0 = (blockIdx.x & 127) * 64;
    int rowA = w * 16 + q;

    // stage Q tile into buf0 (plain loads), extract A fragments
    for (int u = tid; u < 512; u += 128) {
        int r = u >> 3, ch = u & 7;
        *(uint4*)(smf + OFF_KH + r * RB + ch * 16) =
            ((const uint4*)(g_qhi[which] + (size_t)(q0 + r) * D))[ch];
        *(uint4*)(smf + OFF_KL + r * RB + ch * 16) =
            ((const uint4*)(g_qlo[which] + (size_t)(q0 + r) * D))[ch];
    }
    __syncthreads();

    uint32_t aq[2][4][4];
    {
        const uint32_t* ph = (const uint32_t*)(smf + OFF_KH);
        const uint32_t* pl = (const uint32_t*)(smf + OFF_KL);
#pragma unroll
        for (int kk = 0; kk < 4; kk++) {
            int col = kk * 8 + c;
            aq[0][kk][0] = ph[rowA * LS32 + col];
            aq[0][kk][1] = ph[(rowA + 8) * LS32 + col];
            aq[0][kk][2] = ph[rowA * LS32 + col + 4];
            aq[0][kk][3] = ph[(rowA + 8) * LS32 + col + 4];
            aq[1][kk][0] = pl[rowA * LS32 + col];
            aq[1][kk][1] = pl[(rowA + 8) * LS32 + col];
            aq[1][kk][2] = pl[rowA * LS32 + col + 4];
            aq[1][kk][3] = pl[(rowA + 8) * LS32 + col + 4];
        }
    }
    __syncthreads();

    // prologue: prefetch tiles 0 and 1
    flash_issue_tile(sbu, 0, which, 0, tid);
    flash_issue_tile(sbu, 1, which, 64, tid);

    float o[8][4] = {};
    float m0 = -INFINITY, m1 = -INFINITY, l0 = 0.f, l1 = 0.f;
    uint32_t lmoff = (uint32_t)(lane & 7) * RB + (uint32_t)(lane >> 3) * 16;

    int bi = 0, bi2 = 2;   // current buffer, prefetch buffer
    for (int t = 0; t < 128; t++) {
        if (t < 126) cp_wait<1>(); else cp_wait<0>();
        __syncthreads();
        if (t + 2 < 128) flash_issue_tile(sbu, bi2, which, (t + 2) * 64, tid);
        uint32_t bufb = sbu + (uint32_t)bi * TILE_B;
        bi = (bi == 2) ? 0 : bi + 1;
        bi2 = (bi2 == 2) ? 0 : bi2 + 1;

        // ---- S = Q K^T (3 split passes: hh, hl, lh) ----
        float sc[8][4] = {};
#pragma unroll
        for (int nt = 0; nt < 8; nt++) {
            uint32_t a0 = bufb + (uint32_t)nt * (8 * RB) + lmoff;
            uint32_t bh[4][2], bl[4][2];
            ldmx4(&bh[0][0], a0 + OFF_KH);
            ldmx4(&bh[2][0], a0 + OFF_KH + 64);
            ldmx4(&bl[0][0], a0 + OFF_KL);
            ldmx4(&bl[2][0], a0 + OFF_KL + 64);
#pragma unroll
            for (int kk = 0; kk < 4; kk++) mma16816(sc[nt], aq[0][kk], bh[kk]);
#pragma unroll
            for (int kk = 0; kk < 4; kk++) mma16816(sc[nt], aq[0][kk], bl[kk]);
#pragma unroll
            for (int kk = 0; kk < 4; kk++) mma16816(sc[nt], aq[1][kk], bh[kk]);
        }

        // ---- online softmax ----
        float mx0 = -INFINITY, mx1 = -INFINITY;
#pragma unroll
        for (int nt = 0; nt < 8; nt++) {
            mx0 = fmaxf(mx0, fmaxf(sc[nt][0], sc[nt][1]));
            mx1 = fmaxf(mx1, fmaxf(sc[nt][2], sc[nt][3]));
        }
        mx0 = fmaxf(mx0, __shfl_xor_sync(0xffffffffu, mx0, 1));
        mx0 = fmaxf(mx0, __shfl_xor_sync(0xffffffffu, mx0, 2));
        mx1 = fmaxf(mx1, __shfl_xor_sync(0xffffffffu, mx1, 1));
        mx1 = fmaxf(mx1, __shfl_xor_sync(0xffffffffu, mx1, 2));
        float m0n = fmaxf(m0, mx0), m1n = fmaxf(m1, mx1);
        float f0 = __expf(SCALE * (m0 - m0n));
        float f1 = __expf(SCALE * (m1 - m1n));
        m0 = m0n; m1 = m1n;
        l0 *= f0; l1 *= f1;

        uint32_t pah[8], pbh[8], pal[8], pbl[8];
#pragma unroll
        for (int nt = 0; nt < 8; nt++) {
            float p0 = __expf(SCALE * (sc[nt][0] - m0));
            float p1 = __expf(SCALE * (sc[nt][1] - m0));
            float p2 = __expf(SCALE * (sc[nt][2] - m1));
            float p3 = __expf(SCALE * (sc[nt][3] - m1));
            l0 += p0 + p1; l1 += p2 + p3;
            uint32_t h = pack_bf16x2(p0, p1);
            pah[nt] = h;
            pal[nt] = pack_bf16x2(p0 - lo_bf16(h), p1 - hi_bf16(h));
            h = pack_bf16x2(p2, p3);
            pbh[nt] = h;
            pbl[nt] = pack_bf16x2(p2 - lo_bf16(h), p3 - hi_bf16(h));
            o[nt][0] *= f0; o[nt][1] *= f0; o[nt][2] *= f1; o[nt][3] *= f1;
        }

        // ---- O += P V (3 split passes), row-major V via ldmatrix.trans ----
#pragma unroll
        for (int nt = 0; nt < 8; nt++) {
            uint32_t av = bufb + OFF_VH + (uint32_t)lane * RB + (uint32_t)nt * 16;
            uint32_t vbh[4][2], vbl[4][2];
            ldmx4t(&vbh[0][0], av);
            ldmx4t(&vbh[2][0], av + 32 * RB);
            ldmx4t(&vbl[0][0], av + (OFF_VL - OFF_VH));
            ldmx4t(&vbl[2][0], av + (OFF_VL - OFF_VH) + 32 * RB);
#pragma unroll
            for (int kk = 0; kk < 4; kk++) {
                uint32_t Ah[4] = {pah[2 * kk], pbh[2 * kk], pah[2 * kk + 1], pbh[2 * kk + 1]};
                uint32_t Al[4] = {pal[2 * kk], pbl[2 * kk], pal[2 * kk + 1], pbl[2 * kk + 1]};
                mma16816(o[nt], Ah, vbh[kk]);
                mma16816(o[nt], Ah, vbl[kk]);
                mma16816(o[nt], Al, vbh[kk]);
            }
        }
    }

    // ---- epilogue ----
    l0 += __shfl_xor_sync(0xffffffffu, l0, 1);
    l0 += __shfl_xor_sync(0xffffffffu, l0, 2);
    l1 += __shfl_xor_sync(0xffffffffu, l1, 1);
    l1 += __shfl_xor_sync(0xffffffffu, l1, 2);
    float inv0 = 1.0f / l0, inv1 = 1.0f / l1;
    float n0 = 0.f, n1 = 0.f;
    int row = q0 + rowA;
    uint32_t* dh = (uint32_t*)g_atthi[which];
    uint32_t* dl = (uint32_t*)g_attlo[which];
#pragma unroll
    for (int nt = 0; nt < 8; nt++) {
        float o0 = o[nt][0] * inv0, o1 = o[nt][1] * inv0;
        float o2 = o[nt][2] * inv1, o3 = o[nt][3] * inv1;
        n0 = fmaf(o0, o0, fmaf(o1, o1, n0));
        n1 = fmaf(o2, o2, fmaf(o3, o3, n1));
        uint32_t h = pack_bf16x2(o0, o1);
        dh[(size_t)row * 32 + nt * 4 + c] = h;
        dl[(size_t)row * 32 + nt * 4 + c] = pack_bf16x2(o0 - lo_bf16(h), o1 - hi_bf16(h));
        h = pack_bf16x2(o2, o3);
        dh[(size_t)(row + 8) * 32 + nt * 4 + c] = h;
        dl[(size_t)(row + 8) * 32 + nt * 4 + c] = pack_bf16x2(o2 - lo_bf16(h), o3 - hi_bf16(h));
    }
    n0 += __shfl_xor_sync(0xffffffffu, n0, 1);
    n0 += __shfl_xor_sync(0xffffffffu, n0, 2);
    n1 += __shfl_xor_sync(0xffffffffu, n1, 1);
    n1 += __shfl_xor_sync(0xffffffffu, n1, 2);
    if (c == 0) {
        g_norm2[which][row] = n0;
        g_norm2[which][row + 8] = n1;
    }
}

// ---------------------------------------------------------------------------
// kernel 3: pairwise RBF via mma.sync (64x64 tile, 3-pass split, ldmatrix)
// ---------------------------------------------------------------------------
__global__ __launch_bounds__(128, 3) void pairwise_mma_kernel(float* __restrict__ out) {
    __shared__ __nv_bfloat16 sAh[64 * LSTRIDE];
    __shared__ __nv_bfloat16 sAl[64 * LSTRIDE];
    __shared__ __nv_bfloat16 sBh[64 * LSTRIDE];
    __shared__ __nv_bfloat16 sBl[64 * LSTRIDE];
    __shared__ float syn[64];

    int tid = threadIdx.x;
    int w = tid >> 5, lane = tid & 31;
    int q = lane >> 2, c = lane & 3;
    int m0 = blockIdx.y * 64;
    int j0 = blockIdx.x * 64;
    int rowA = w * 16 + q;

    for (int u = tid; u < 512; u += 128) {
        int r = u >> 3, ch = u & 7;
        ((uint4*)(sAh + r * LSTRIDE))[ch] = ((const uint4*)(g_atthi[0] + (size_t)(m0 + r) * D))[ch];
        ((uint4*)(sAl + r * LSTRIDE))[ch] = ((const uint4*)(g_attlo[0] + (size_t)(m0 + r) * D))[ch];
        ((uint4*)(sBh + r * LSTRIDE))[ch] = ((const uint4*)(g_atthi[1] + (size_t)(j0 + r) * D))[ch];
        ((uint4*)(sBl + r * LSTRIDE))[ch] = ((const uint4*)(g_attlo[1] + (size_t)(j0 + r) * D))[ch];
    }
    if (tid < 64) syn[tid] = g_norm2[1][j0 + tid];
    __syncthreads();

    uint32_t aq[2][4][4];
    {
        const uint32_t* ph = (const uint32_t*)sAh;
        const uint32_t* pl = (const uint32_t*)sAl;
#pragma unroll
        for (int kk = 0; kk < 4; kk++) {
            int col = kk * 8 + c;
            aq[0][kk][0] = ph[rowA * LS32 + col];
            aq[0][kk][1] = ph[(rowA + 8) * LS32 + col];
            aq[0][kk][2] = ph[rowA * LS32 + col + 4];
            aq[0][kk][3] = ph[(rowA + 8) * LS32 + col + 4];
            aq[1][kk][0] = pl[rowA * LS32 + col];
            aq[1][kk][1] = pl[(rowA + 8) * LS32 + col];
            aq[1][kk][2] = pl[rowA * LS32 + col + 4];
            aq[1][kk][3] = pl[(rowA + 8) * LS32 + col + 4];
        }
    }

    uint32_t sbh = smem_u32(sBh), sbl = smem_u32(sBl);
    uint32_t lmoff = (uint32_t)(lane & 7) * RB + (uint32_t)(lane >> 3) * 16;
    float acc[8][4] = {};
#pragma unroll
    for (int nt = 0; nt < 8; nt++) {
        uint32_t ro = (uint32_t)nt * (8 * RB) + lmoff;
        uint32_t bh[4][2], bl[4][2];
        ldmx4(&bh[0][0], sbh + ro);
        ldmx4(&bh[2][0], sbh + ro + 64);
        ldmx4(&bl[0][0], sbl + ro);
        ldmx4(&bl[2][0], sbl + ro + 64);
#pragma unroll
        for (int kk = 0; kk < 4; kk++) mma16816(acc[nt], aq[0][kk], bh[kk]);
#pragma unroll
        for (int kk = 0; kk < 4; kk++) mma16816(acc[nt], aq[0][kk], bl[kk]);
#pragma unroll
        for (int kk = 0; kk < 4; kk++) mma16816(acc[nt], aq[1][kk], bh[kk]);
    }

    int rowx = m0 + rowA;
    float xn0 = g_norm2[0][rowx];
    float xn1 = g_norm2[0][rowx + 8];
#pragma unroll
    for (int nt = 0; nt < 8; nt++) {
        int cb = nt * 8 + 2 * c;
        float y0 = syn[cb], y1 = syn[cb + 1];
        float2 e;
        e.x = __expf(-(xn0 + y0 - 2.f * acc[nt][0]));
        e.y = __expf(-(xn0 + y1 - 2.f * acc[nt][1]));
        *reinterpret_cast<float2*>(out + (size_t)rowx * N + j0 + cb) = e;
        e.x = __expf(-(xn1 + y0 - 2.f * acc[nt][2]));
        e.y = __expf(-(xn1 + y1 - 2.f * acc[nt][3]));
        *reinterpret_cast<float2*>(out + (size_t)(rowx + 8) * N + j0 + cb) = e;
    }
}

// ---------------------------------------------------------------------------
extern "C" void kernel_launch(void* const* d_in, const int* in_sizes, int n_in,
                              void* d_out, int out_size) {
    const float* Wq = (const float*)d_in[0];
    const float* Wk = (const float*)d_in[1];
    const float* x  = (const float*)d_in[2];
    const float* y  = (const float*)d_in[3];
    float* out = (float*)d_out;

    prep_kernel<<<256, 256>>>(x, y, Wq, Wk);

    cudaFuncSetAttribute(flash_mma_kernel, cudaFuncAttributeMaxDynamicSharedMemorySize,
                         SMEM_FLASH);
    flash_mma_kernel<<<256, 128, SMEM_FLASH>>>();

    dim3 grid(N / 64, N / 64);
    pairwise_mma_kernel<<<grid, 128>>>(out);
}